// round 1
// baseline (speedup 1.0000x reference)
#include <cuda_runtime.h>
#include <cstdint>

#define N_NODES 50000
#define N_EDGES 800000
#define DIM     64
#define N_REL   16

// ---------------- scratch (device globals: allocation-free) ----------------
__device__ float    g_proj[(size_t)N_REL * N_NODES * DIM];  // 204.8 MB
__device__ float    g_att[N_EDGES];                          // att, then exp(att-max)
__device__ float    g_denom[N_NODES];
__device__ unsigned g_maxenc[N_NODES];

// ---------------- helpers ----------------
__device__ __forceinline__ unsigned enc_f(float f) {
    unsigned u = __float_as_uint(f);
    return (u & 0x80000000u) ? ~u : (u | 0x80000000u);
}
__device__ __forceinline__ float dec_f(unsigned e) {
    unsigned u = (e & 0x80000000u) ? (e & 0x7fffffffu) : ~e;
    return __uint_as_float(u);
}
__device__ __forceinline__ float fast_tanh(float x) {
    float xc = fminf(fmaxf(x, -15.f), 15.f);
    float t  = __expf(2.f * xc);
    return __fdividef(t - 1.f, t + 1.f);
}
__device__ __forceinline__ unsigned long long pack2(float x) {
    unsigned long long r;
    asm("mov.b64 %0, {%1, %1};" : "=l"(r) : "f"(x));
    return r;
}
__device__ __forceinline__ void ffma2(unsigned long long& d,
                                      unsigned long long a,
                                      unsigned long long b) {
    asm("fma.rn.f32x2 %0, %1, %2, %0;" : "+l"(d) : "l"(a), "l"(b));
}
__device__ __forceinline__ void unpack2(unsigned long long v, float& lo, float& hi) {
    asm("mov.b64 {%0, %1}, %2;" : "=f"(lo), "=f"(hi) : "l"(v));
}
__device__ __forceinline__ float leaky(float x) { return x >= 0.f ? x : 0.01f * x; }

// ---------------- K0: init ----------------
__global__ void init_kernel(float* __restrict__ out) {
    int i = blockIdx.x * blockDim.x + threadIdx.x;
    if (i < 2 * N_NODES * DIM) out[i] = 0.f;
    if (i < N_NODES) { g_denom[i] = 0.f; g_maxenc[i] = 0u; }
}

// ---------------- K1: proj[r,n,:] = nfeat[n,:] @ W_r  (f32x2 packed FMA) ----
// Block: 128 threads, tile = 128 nodes of one relation.
// Thread (cg = tid&3, tr = tid>>2): nodes tr*4..tr*4+3, cols cg*16..cg*16+15.
__global__ void __launch_bounds__(128) proj_kernel(const float* __restrict__ nfeat,
                                                   const float* __restrict__ relW) {
    __shared__ __align__(16) float Ws[64 * 64];     // 16 KB, [d][e]
    __shared__ __align__(16) float Xs[64 * 128];    // 32 KB, transposed [d][node]

    const int r   = blockIdx.y;
    const int n0  = blockIdx.x * 128;
    const int tid = threadIdx.x;

    // load W_r (coalesced float4)
    {
        const float4* wsrc = (const float4*)(relW + (size_t)r * 4096);
        float4* wdst = (float4*)Ws;
        #pragma unroll
        for (int i = tid; i < 1024; i += 128) wdst[i] = wsrc[i];
    }
    // load X tile transposed: thread tid handles node n0+tid
    {
        int n = n0 + tid;
        if (n < N_NODES) {
            const float4* nr = (const float4*)(nfeat + (size_t)n * DIM);
            #pragma unroll
            for (int c4 = 0; c4 < 16; c4++) {
                float4 v = nr[c4];
                Xs[(c4 * 4 + 0) * 128 + tid] = v.x;
                Xs[(c4 * 4 + 1) * 128 + tid] = v.y;
                Xs[(c4 * 4 + 2) * 128 + tid] = v.z;
                Xs[(c4 * 4 + 3) * 128 + tid] = v.w;
            }
        } else {
            #pragma unroll
            for (int c = 0; c < 64; c++) Xs[c * 128 + tid] = 0.f;
        }
    }
    __syncthreads();

    const int cg = tid & 3;
    const int tr = tid >> 2;

    unsigned long long acc[4][8];
    #pragma unroll
    for (int m = 0; m < 4; m++)
        #pragma unroll
        for (int j = 0; j < 8; j++) acc[m][j] = 0ull;

    #pragma unroll 8
    for (int d = 0; d < 64; d++) {
        unsigned long long w2[8];
        const float* wrow = Ws + d * 64 + cg * 16;
        #pragma unroll
        for (int j = 0; j < 8; j++)
            w2[j] = *(const unsigned long long*)(wrow + 2 * j);
        #pragma unroll
        for (int m = 0; m < 4; m++) {
            unsigned long long x2 = pack2(Xs[d * 128 + tr * 4 + m]);
            #pragma unroll
            for (int j = 0; j < 8; j++) ffma2(acc[m][j], x2, w2[j]);
        }
    }

    #pragma unroll
    for (int m = 0; m < 4; m++) {
        int n = n0 + tr * 4 + m;
        if (n >= N_NODES) continue;
        float* orow = g_proj + ((size_t)r * N_NODES + n) * DIM + cg * 16;
        #pragma unroll
        for (int j = 0; j < 8; j++) {
            float lo, hi;
            unpack2(acc[m][j], lo, hi);
            orow[2 * j]     = lo;
            orow[2 * j + 1] = hi;
        }
    }
}

// ---------------- K2: per-edge attention logit + segment max ----------------
__global__ void __launch_bounds__(256) att_kernel(const float* __restrict__ efeat,
                                                  const int* __restrict__ src,
                                                  const int* __restrict__ dst,
                                                  const int* __restrict__ etype) {
    int gt   = blockIdx.x * blockDim.x + threadIdx.x;
    int e    = gt >> 5;
    int lane = threadIdx.x & 31;
    if (e >= N_EDGES) return;

    int s = src[e], d = dst[e], r = etype[e];
    const float2* t2 = (const float2*)(g_proj + ((size_t)r * N_NODES + s) * DIM);
    const float2* h2 = (const float2*)(g_proj + ((size_t)r * N_NODES + d) * DIM);
    const float2* e2 = (const float2*)(efeat + (size_t)e * DIM);

    float2 tv = t2[lane], hv = h2[lane], ev = e2[lane];
    float val = tv.x * fast_tanh(hv.x + ev.x) + tv.y * fast_tanh(hv.y + ev.y);

    #pragma unroll
    for (int off = 16; off; off >>= 1) val += __shfl_xor_sync(0xffffffffu, val, off);

    if (lane == 0) {
        g_att[e] = val;
        atomicMax(&g_maxenc[d], enc_f(val));
    }
}

// ---------------- K3: exp(att - max) + segment sum ----------------
__global__ void __launch_bounds__(256) softmax_kernel(const int* __restrict__ dst) {
    int e = blockIdx.x * blockDim.x + threadIdx.x;
    if (e >= N_EDGES) return;
    int d = dst[e];
    float m  = dec_f(g_maxenc[d]);
    float ex = __expf(g_att[e] - m);
    g_att[e] = ex;
    atomicAdd(&g_denom[d], ex);
}

// ---------------- K4: h_neighbor[dst] += a * nfeat[src]  (float4 atomics) ---
__global__ void __launch_bounds__(256) agg_kernel(const float* __restrict__ nfeat,
                                                  const int* __restrict__ src,
                                                  const int* __restrict__ dst,
                                                  float* __restrict__ hnb) {
    int gt = blockIdx.x * blockDim.x + threadIdx.x;
    int e  = gt >> 4;                 // 16 lanes per edge
    int sl = threadIdx.x & 15;
    if (e >= N_EDGES) return;

    int s = src[e], d = dst[e];
    float a = g_att[e] / g_denom[d];

    float4 v = ((const float4*)(nfeat + (size_t)s * DIM))[sl];
    float4 w = make_float4(v.x * a, v.y * a, v.z * a, v.w * a);
    float4* p = ((float4*)(hnb + (size_t)d * DIM)) + sl;
#if defined(__CUDA_ARCH__) && (__CUDA_ARCH__ >= 900)
    atomicAdd(p, w);
#else
    float* pf = (float*)p;
    atomicAdd(pf + 0, w.x);
    atomicAdd(pf + 1, w.y);
    atomicAdd(pf + 2, w.z);
    atomicAdd(pf + 3, w.w);
#endif
}

// ---------------- K5: out (+)= leaky((nfeat OP hnb) @ W) ----------------
// MODE 0: OP = '+', MODE 1: OP = '*'. Block: 128 threads, tile = 64 nodes.
template <int MODE>
__global__ void __launch_bounds__(128) out_gemm_kernel(const float* __restrict__ nfeat,
                                                       const float* __restrict__ hnb,
                                                       const float* __restrict__ W,
                                                       float* __restrict__ out,
                                                       int accumulate) {
    __shared__ __align__(16) float Ws[64 * 64];   // 16 KB [d][e]
    __shared__ __align__(16) float Ss[64 * 64];   // 16 KB transposed [d][node]

    const int n0  = blockIdx.x * 64;
    const int tid = threadIdx.x;

    {
        const float4* wsrc = (const float4*)W;
        float4* wdst = (float4*)Ws;
        #pragma unroll
        for (int i = tid; i < 1024; i += 128) wdst[i] = wsrc[i];
    }
    {
        int nn = tid & 63;
        int n  = n0 + nn;
        if (n < N_NODES) {
            const float4* a4 = (const float4*)(nfeat + (size_t)n * DIM);
            const float4* b4 = (const float4*)(hnb  + (size_t)n * DIM);
            for (int c4 = (tid >> 6); c4 < 16; c4 += 2) {
                float4 a = a4[c4], b = b4[c4];
                float4 sv;
                if (MODE == 0) sv = make_float4(a.x + b.x, a.y + b.y, a.z + b.z, a.w + b.w);
                else           sv = make_float4(a.x * b.x, a.y * b.y, a.z * b.z, a.w * b.w);
                Ss[(c4 * 4 + 0) * 64 + nn] = sv.x;
                Ss[(c4 * 4 + 1) * 64 + nn] = sv.y;
                Ss[(c4 * 4 + 2) * 64 + nn] = sv.z;
                Ss[(c4 * 4 + 3) * 64 + nn] = sv.w;
            }
        } else {
            for (int c4 = (tid >> 6); c4 < 16; c4 += 2) {
                Ss[(c4 * 4 + 0) * 64 + nn] = 0.f;
                Ss[(c4 * 4 + 1) * 64 + nn] = 0.f;
                Ss[(c4 * 4 + 2) * 64 + nn] = 0.f;
                Ss[(c4 * 4 + 3) * 64 + nn] = 0.f;
            }
        }
    }
    __syncthreads();

    const int cg = tid & 3;
    const int tr = tid >> 2;

    unsigned long long acc[2][8];
    #pragma unroll
    for (int m = 0; m < 2; m++)
        #pragma unroll
        for (int j = 0; j < 8; j++) acc[m][j] = 0ull;

    #pragma unroll 8
    for (int d = 0; d < 64; d++) {
        unsigned long long w2[8];
        const float* wrow = Ws + d * 64 + cg * 16;
        #pragma unroll
        for (int j = 0; j < 8; j++)
            w2[j] = *(const unsigned long long*)(wrow + 2 * j);
        #pragma unroll
        for (int m = 0; m < 2; m++) {
            unsigned long long x2 = pack2(Ss[d * 64 + tr * 2 + m]);
            #pragma unroll
            for (int j = 0; j < 8; j++) ffma2(acc[m][j], x2, w2[j]);
        }
    }

    #pragma unroll
    for (int m = 0; m < 2; m++) {
        int n = n0 + tr * 2 + m;
        if (n >= N_NODES) continue;
        float* orow = out + (size_t)n * DIM + cg * 16;
        #pragma unroll
        for (int j = 0; j < 8; j++) {
            float lo, hi;
            unpack2(acc[m][j], lo, hi);
            lo = leaky(lo);
            hi = leaky(hi);
            if (accumulate) { orow[2 * j] += lo; orow[2 * j + 1] += hi; }
            else            { orow[2 * j]  = lo; orow[2 * j + 1]  = hi; }
        }
    }
}

// ---------------- launch ----------------
extern "C" void kernel_launch(void* const* d_in, const int* in_sizes, int n_in,
                              void* d_out, int out_size) {
    const float* nfeat = (const float*)d_in[0];
    const float* efeat = (const float*)d_in[1];
    const float* relW  = (const float*)d_in[2];
    const float* W1    = (const float*)d_in[3];
    const float* W2    = (const float*)d_in[4];
    const int*   src   = (const int*)d_in[5];
    const int*   dst   = (const int*)d_in[6];
    const int*   etype = (const int*)d_in[7];

    float* hnb  = (float*)d_out;                       // first N*D floats
    float* out2 = (float*)d_out + (size_t)N_NODES * DIM;

    init_kernel<<<(2 * N_NODES * DIM + 255) / 256, 256>>>((float*)d_out);

    dim3 g1((N_NODES + 127) / 128, N_REL);
    proj_kernel<<<g1, 128>>>(nfeat, relW);

    att_kernel<<<(N_EDGES * 32 + 255) / 256, 256>>>(efeat, src, dst, etype);
    softmax_kernel<<<(N_EDGES + 255) / 256, 256>>>(dst);
    agg_kernel<<<(N_EDGES * 16 + 255) / 256, 256>>>(nfeat, src, dst, hnb);

    out_gemm_kernel<0><<<(N_NODES + 63) / 64, 128>>>(nfeat, hnb, W1, out2, 0);
    out_gemm_kernel<1><<<(N_NODES + 63) / 64, 128>>>(nfeat, hnb, W2, out2, 1);
}